// round 7
// baseline (speedup 1.0000x reference)
#include <cuda_runtime.h>
#include <cuda_bf16.h>
#include <cstdint>

#define BB 64
#define TT 72
#define SS 72
#define EE 128
#define HH 256
#define VV 32000
#define KK 512
#define NTILE 256
#define KCH 64
#define NCH (KK / KCH)   // 8

typedef unsigned long long ull;

// ---------------- device scratch (static, allocation-free) ----------------
__device__ float g_c[BB * HH];
__device__ float g_h[2][BB][HH];                 // natural layout h
__device__ __nv_bfloat16 g_Ah[2][BB][KK];        // state hi
__device__ __nv_bfloat16 g_Al[2][BB][KK];        // state lo
__device__ __nv_bfloat16 g_Wh[(size_t)VV * KK];  // W_lin hi (32.8 MB)
__device__ __nv_bfloat16 g_Wl[(size_t)VV * KK];  // W_lin lo (32.8 MB)

// ---------------- PTX helpers ----------------
__device__ __forceinline__ uint32_t smem_u32(const void* p) {
    uint32_t a;
    asm("{ .reg .u64 t; cvta.to.shared.u64 t, %1; cvt.u32.u64 %0, t; }"
        : "=r"(a) : "l"(p));
    return a;
}
__device__ __forceinline__ void cp16(uint32_t dst_smem, const void* src) {
    asm volatile("cp.async.cg.shared.global [%0], [%1], 16;"
                 :: "r"(dst_smem), "l"(src));
}
#define CP_COMMIT() asm volatile("cp.async.commit_group;")
#define CP_WAIT1()  asm volatile("cp.async.wait_group 1;" ::: "memory")
#define CP_WAIT0()  asm volatile("cp.async.wait_group 0;" ::: "memory")

__device__ __forceinline__ void ldm_x4(uint32_t a, uint32_t* r) {
    asm volatile("ldmatrix.sync.aligned.m8n8.x4.shared.b16 {%0,%1,%2,%3}, [%4];"
                 : "=r"(r[0]), "=r"(r[1]), "=r"(r[2]), "=r"(r[3]) : "r"(a));
}
__device__ __forceinline__ void ldm_x2(uint32_t a, uint32_t* r) {
    asm volatile("ldmatrix.sync.aligned.m8n8.x2.shared.b16 {%0,%1}, [%2];"
                 : "=r"(r[0]), "=r"(r[1]) : "r"(a));
}
__device__ __forceinline__ void mma_bf16(float* c, const uint32_t* a,
                                         const uint32_t* b) {
    asm volatile(
        "mma.sync.aligned.m16n8k16.row.col.f32.bf16.bf16.f32 "
        "{%0,%1,%2,%3}, {%4,%5,%6,%7}, {%8,%9}, {%0,%1,%2,%3};"
        : "+f"(c[0]), "+f"(c[1]), "+f"(c[2]), "+f"(c[3])
        : "r"(a[0]), "r"(a[1]), "r"(a[2]), "r"(a[3]), "r"(b[0]), "r"(b[1]));
}

__device__ __forceinline__ uint32_t sw128(uint32_t off) {
    return off ^ ((off >> 3) & 0x70);
}
__device__ __forceinline__ float sigf(float x) { return 1.0f / (1.0f + __expf(-x)); }

// ---------------- one-time prep ----------------
__global__ void convert_W(const float* __restrict__ W) {
    size_t i = (size_t)blockIdx.x * blockDim.x + threadIdx.x;
    float w = W[i];
    __nv_bfloat16 hi = __float2bfloat16(w);
    g_Wh[i] = hi;
    g_Wl[i] = __float2bfloat16(w - __bfloat162float(hi));
}
__global__ void init_state(const float* __restrict__ h0, const float* __restrict__ c0) {
    int b = blockIdx.x, j = threadIdx.x;
    g_h[0][b][j]    = h0[b * HH + j];
    g_c[b * HH + j] = c0[b * HH + j];
}

// ---------------- LSTM step ----------------
__global__ void __launch_bounds__(128) lstm_step(
    int t, int rd, int wr,
    const int* __restrict__ target, const float* __restrict__ emb,
    const float* __restrict__ W_ih, const float* __restrict__ W_hh,
    const float* __restrict__ b_ih, const float* __restrict__ b_hh)
{
    __shared__ float sx[4][EE];
    __shared__ float sh[4][HH];
    __shared__ float sg[4][32][4];

    int tid = threadIdx.x;
    int j0 = blockIdx.x * 32;
    int b0 = blockIdx.y * 4;

#pragma unroll
    for (int i = 0; i < 4; i++) {
        int idx = tid + i * 128;
        int bl = idx >> 7, k = idx & 127;
        int tok = target[(b0 + bl) * TT + t];
        sx[bl][k] = emb[(size_t)tok * EE + k];
    }
#pragma unroll
    for (int i = 0; i < 8; i++) {
        int idx = tid + i * 128;
        int bl = idx >> 8, j = idx & 255;
        sh[bl][j] = g_h[rd][b0 + bl][j];
    }
    __syncthreads();

    int gate = tid >> 5, jl = tid & 31;
    int row = gate * HH + j0 + jl;
    float bias = b_ih[row] + b_hh[row];
    float acc[4] = {bias, bias, bias, bias};

    const float4* wih = (const float4*)(W_ih + (size_t)row * EE);
#pragma unroll 8
    for (int kq = 0; kq < EE / 4; kq++) {
        float4 w = wih[kq];
#pragma unroll
        for (int bl = 0; bl < 4; bl++) {
            float4 x = *(const float4*)&sx[bl][kq * 4];
            acc[bl] = fmaf(w.x, x.x, acc[bl]);
            acc[bl] = fmaf(w.y, x.y, acc[bl]);
            acc[bl] = fmaf(w.z, x.z, acc[bl]);
            acc[bl] = fmaf(w.w, x.w, acc[bl]);
        }
    }
    const float4* whh = (const float4*)(W_hh + (size_t)row * HH);
#pragma unroll 8
    for (int kq = 0; kq < HH / 4; kq++) {
        float4 w = whh[kq];
#pragma unroll
        for (int bl = 0; bl < 4; bl++) {
            float4 h = *(const float4*)&sh[bl][kq * 4];
            acc[bl] = fmaf(w.x, h.x, acc[bl]);
            acc[bl] = fmaf(w.y, h.y, acc[bl]);
            acc[bl] = fmaf(w.z, h.z, acc[bl]);
            acc[bl] = fmaf(w.w, h.w, acc[bl]);
        }
    }
#pragma unroll
    for (int bl = 0; bl < 4; bl++) sg[gate][jl][bl] = acc[bl];
    __syncthreads();

    {
        int jl2 = tid >> 2, bl2 = tid & 3;
        float gi = sg[0][jl2][bl2];
        float gf = sg[1][jl2][bl2];
        float gg = sg[2][jl2][bl2];
        float go = sg[3][jl2][bl2];
        int j = j0 + jl2, b = b0 + bl2;
        float c_old = g_c[b * HH + j];
        float c_new = sigf(gf) * c_old + sigf(gi) * tanhf(gg);
        float h_new = sigf(go) * tanhf(c_new);
        g_c[b * HH + j] = c_new;
        g_h[wr][b][j]   = h_new;
        __nv_bfloat16 hi = __float2bfloat16(h_new);
        g_Ah[wr][b][j] = hi;
        g_Al[wr][b][j] = __float2bfloat16(h_new - __bfloat162float(hi));
    }
}

// ---------------- attention ----------------
__global__ void __launch_bounds__(512) attn_step(
    int cur, const float* __restrict__ enc, const int* __restrict__ lens)
{
    extern __shared__ float sm[];
    float (*se)[HH] = (float(*)[HH])sm;       // [72][256]
    float* sw   = sm + SS * HH;               // [72]
    float* part = sw + SS;                    // [2][256]
    __shared__ float shv[HH];
    __shared__ float sred;

    int b = blockIdx.x, tid = threadIdx.x;

    const float4* esrc = (const float4*)(enc + (size_t)b * SS * HH);
    float4* sdst = (float4*)se;
#pragma unroll
    for (int i = 0; i < 9; i++) sdst[tid + i * 512] = esrc[tid + i * 512];
    if (tid < HH) shv[tid] = g_h[cur][b][tid];
    __syncthreads();

    int len = lens[b];
    int w = tid >> 5, lane = tid & 31;
    for (int s = w; s < SS; s += 16) {
        float acc = 0.f;
#pragma unroll
        for (int j = lane; j < HH; j += 32) acc += shv[j] * se[s][j];
#pragma unroll
        for (int o = 16; o; o >>= 1) acc += __shfl_xor_sync(0xffffffffu, acc, o);
        if (lane == 0) sw[s] = (s < len) ? acc * 0.0625f : -1e30f;
    }
    __syncthreads();

    if (tid < 32) {
        float m = -1e30f;
        for (int s = tid; s < SS; s += 32) m = fmaxf(m, sw[s]);
#pragma unroll
        for (int o = 16; o; o >>= 1) m = fmaxf(m, __shfl_xor_sync(0xffffffffu, m, o));
        float sum = 0.f;
        for (int s = tid; s < SS; s += 32) {
            float e = __expf(sw[s] - m);
            sw[s] = e;
            sum += e;
        }
#pragma unroll
        for (int o = 16; o; o >>= 1) sum += __shfl_xor_sync(0xffffffffu, sum, o);
        if (tid == 0) sred = 1.0f / sum;
    }
    __syncthreads();

    {
        int j = tid & 255, half = tid >> 8;
        int s0 = half * 36;
        float acc = 0.f;
#pragma unroll
        for (int s = 0; s < 36; s++) acc += sw[s0 + s] * se[s0 + s][j];
        part[half * 256 + j] = acc;
    }
    __syncthreads();
    if (tid < 256) {
        float ctx = (part[tid] + part[256 + tid]) * sred;
        __nv_bfloat16 hi = __float2bfloat16(ctx);
        g_Ah[cur][b][HH + tid] = hi;
        g_Al[cur][b][HH + tid] = __float2bfloat16(ctx - __bfloat162float(hi));
    }
}

// ---------------- output projection: HMMA bf16-split GEMM ----------------
// 125 CTAs x 512 threads (16 warps, 4/SMSP). CTA tile 64M x 256N.
// Warp grid 2M x 8N; warp tile 32M x 32N. K-chunks of 64 bf16 (SW128).
// cp.async double buffer, 160 KB smem.
#define OFF_AL 8192
#define OFF_BH 16384
#define OFF_BL 49152
#define STAGE  81920

__global__ void __launch_bounds__(512) gemm_step(
    int t, int cur, const float* __restrict__ b_lin, float* __restrict__ out)
{
    extern __shared__ __align__(1024) char smc[];
    uint32_t sb = smem_u32(smc);
    int tid = threadIdx.x, wid = tid >> 5, lane = tid & 31;
    int n0g = blockIdx.x * NTILE;
    int wm = wid & 1;        // M half: 0 or 32
    int wn = wid >> 1;       // N group: 0..7 (32 cols each)

    // ---- chunk loader (512 threads) ----
    auto load_chunk = [&](int ko, int s) {
        int k0 = ko * KCH;
        uint32_t base = sb + s * STAGE;
        {                                              // A: 64 rows x 8 segs = 512
            int r = tid >> 3, sg = tid & 7;
            uint32_t o = sw128((uint32_t)(r * 128 + sg * 16));
            cp16(base + o,          &g_Ah[cur][r][k0 + sg * 8]);
            cp16(base + OFF_AL + o, &g_Al[cur][r][k0 + sg * 8]);
        }
#pragma unroll
        for (int i = 0; i < 4; i++) {                  // B: 256 rows x 8 segs = 2048
            int idx = tid + i * 512;
            int r = idx >> 3, sg = idx & 7;
            uint32_t o = sw128((uint32_t)(r * 128 + sg * 16));
            size_t gi = (size_t)(n0g + r) * KK + k0 + sg * 8;
            cp16(base + OFF_BH + o, &g_Wh[gi]);
            cp16(base + OFF_BL + o, &g_Wl[gi]);
        }
        CP_COMMIT();
    };

    float acc[2][4][4];
#pragma unroll
    for (int mt = 0; mt < 2; mt++)
#pragma unroll
        for (int nt = 0; nt < 4; nt++)
#pragma unroll
            for (int r = 0; r < 4; r++) acc[mt][nt][r] = 0.f;

    // per-lane ldmatrix address components
    int l15 = lane & 15;
    int aKhalf = (lane >> 4) * 16;        // A: lanes 16-31 take k+8
    int bKhalf = ((lane >> 3) & 1) * 16;  // B: lanes 8-15 take k+8
    int bRow = lane & 7;

    load_chunk(0, 0);

    for (int ko = 0; ko < NCH; ko++) {
        int buf = ko & 1;
        if (ko + 1 < NCH) {
            load_chunk(ko + 1, buf ^ 1);
            CP_WAIT1();
        } else {
            CP_WAIT0();
        }
        __syncthreads();   // chunk ko visible to all

        uint32_t base = sb + buf * STAGE;
#pragma unroll
        for (int ks = 0; ks < 4; ks++) {
            uint32_t ah[2][4], al[2][4], bh[4][2], blr[4][2];
#pragma unroll
            for (int mt = 0; mt < 2; mt++) {
                uint32_t off = sw128((uint32_t)((wm * 32 + mt * 16 + l15) * 128 +
                                                ks * 32 + aKhalf));
                ldm_x4(base + off, ah[mt]);
                ldm_x4(base + OFF_AL + off, al[mt]);
            }
#pragma unroll
            for (int nt = 0; nt < 4; nt++) {
                uint32_t off = sw128((uint32_t)((wn * 32 + nt * 8 + bRow) * 128 +
                                                ks * 32 + bKhalf));
                ldm_x2(base + OFF_BH + off, bh[nt]);
                ldm_x2(base + OFF_BL + off, blr[nt]);
            }
#pragma unroll
            for (int mt = 0; mt < 2; mt++)
#pragma unroll
                for (int nt = 0; nt < 4; nt++) {
                    mma_bf16(acc[mt][nt], ah[mt], bh[nt]);
                    mma_bf16(acc[mt][nt], ah[mt], blr[nt]);
                    mma_bf16(acc[mt][nt], al[mt], bh[nt]);
                }
        }
        __syncthreads();   // done reading buf before it is overwritten
    }

    // ---- epilogue: fragment regs -> gmem (float2 stores) ----
    int qr = lane >> 2, qc = lane & 3;
#pragma unroll
    for (int nt = 0; nt < 4; nt++) {
        int v = n0g + wn * 32 + nt * 8 + qc * 2;
        float2 bi = *(const float2*)&b_lin[v];
#pragma unroll
        for (int mt = 0; mt < 2; mt++) {
            int bA = wm * 32 + mt * 16 + qr;
            int bBt = bA + 8;
            float2 lo = {acc[mt][nt][0] + bi.x, acc[mt][nt][1] + bi.y};
            float2 hi = {acc[mt][nt][2] + bi.x, acc[mt][nt][3] + bi.y};
            *(float2*)&out[((size_t)(bA * TT + t)) * VV + v]  = lo;
            *(float2*)&out[((size_t)(bBt * TT + t)) * VV + v] = hi;
        }
    }
}

// ---------------- launch ----------------
extern "C" void kernel_launch(void* const* d_in, const int* in_sizes, int n_in,
                              void* d_out, int out_size)
{
    const int*   target = (const int*)d_in[0];
    const float* enc    = (const float*)d_in[1];
    const int*   lens   = (const int*)d_in[2];
    const float* h0     = (const float*)d_in[3];
    const float* c0     = (const float*)d_in[4];
    const float* emb    = (const float*)d_in[5];
    const float* W_ih   = (const float*)d_in[6];
    const float* W_hh   = (const float*)d_in[7];
    const float* b_ih   = (const float*)d_in[8];
    const float* b_hh   = (const float*)d_in[9];
    const float* W_lin  = (const float*)d_in[10];
    const float* b_lin  = (const float*)d_in[11];
    float* out = (float*)d_out;

    const int attn_smem = (SS * HH + SS + 2 * HH) * (int)sizeof(float);
    cudaFuncSetAttribute(attn_step, cudaFuncAttributeMaxDynamicSharedMemorySize,
                         attn_smem);
    const int gemm_smem = 2 * STAGE;   // 160 KB
    cudaFuncSetAttribute(gemm_step, cudaFuncAttributeMaxDynamicSharedMemorySize,
                         gemm_smem);

    convert_W<<<VV * KK / 512, 512>>>(W_lin);
    init_state<<<BB, HH>>>(h0, c0);

    for (int t = 0; t < TT; t++) {
        int rd = t & 1, wr = rd ^ 1;
        lstm_step<<<dim3(HH / 32, BB / 4), 128>>>(t, rd, wr, target, emb,
                                                  W_ih, W_hh, b_ih, b_hh);
        attn_step<<<BB, 512, attn_smem>>>(wr, enc, lens);
        gemm_step<<<VV / NTILE, 512, gemm_smem>>>(t, wr, b_lin, out);
    }
}

// round 8
// speedup vs baseline: 1.0415x; 1.0415x over previous
#include <cuda_runtime.h>
#include <cuda_bf16.h>
#include <cstdint>

#define BB 64
#define TT 72
#define SS 72
#define EE 128
#define HH 256
#define VV 32000
#define KK 512
#define NTILE 256
#define KCH 64
#define NCH (KK / KCH)   // 8
#define NTILES_N (VV / 8)    // 4000
#define NTILES_K (KK / 16)   // 32

typedef unsigned long long ull;

// ---------------- device scratch (static, allocation-free) ----------------
__device__ float g_c[BB * HH];
__device__ float g_h[2][BB][HH];                 // natural layout h
__device__ __nv_bfloat16 g_Ah[2][BB][KK];        // state hi
__device__ __nv_bfloat16 g_Al[2][BB][KK];        // state lo
// W_lin pre-packed in HMMA B-fragment order: [nn][kk][lane] -> u64 {b0,b1}
__device__ ull g_WfH[(size_t)NTILES_N * NTILES_K * 32];   // 32.8 MB
__device__ ull g_WfL[(size_t)NTILES_N * NTILES_K * 32];   // 32.8 MB

// ---------------- PTX helpers ----------------
__device__ __forceinline__ uint32_t smem_u32(const void* p) {
    uint32_t a;
    asm("{ .reg .u64 t; cvta.to.shared.u64 t, %1; cvt.u32.u64 %0, t; }"
        : "=r"(a) : "l"(p));
    return a;
}
__device__ __forceinline__ void cp16(uint32_t dst_smem, const void* src) {
    asm volatile("cp.async.cg.shared.global [%0], [%1], 16;"
                 :: "r"(dst_smem), "l"(src));
}
#define CP_COMMIT() asm volatile("cp.async.commit_group;")
#define CP_WAIT1()  asm volatile("cp.async.wait_group 1;" ::: "memory")
#define CP_WAIT0()  asm volatile("cp.async.wait_group 0;" ::: "memory")

__device__ __forceinline__ void ldm_x4(uint32_t a, uint32_t* r) {
    asm volatile("ldmatrix.sync.aligned.m8n8.x4.shared.b16 {%0,%1,%2,%3}, [%4];"
                 : "=r"(r[0]), "=r"(r[1]), "=r"(r[2]), "=r"(r[3]) : "r"(a));
}
__device__ __forceinline__ void mma_bf16(float* c, const uint32_t* a,
                                         uint32_t b0, uint32_t b1) {
    asm volatile(
        "mma.sync.aligned.m16n8k16.row.col.f32.bf16.bf16.f32 "
        "{%0,%1,%2,%3}, {%4,%5,%6,%7}, {%8,%9}, {%0,%1,%2,%3};"
        : "+f"(c[0]), "+f"(c[1]), "+f"(c[2]), "+f"(c[3])
        : "r"(a[0]), "r"(a[1]), "r"(a[2]), "r"(a[3]), "r"(b0), "r"(b1));
}

__device__ __forceinline__ uint32_t sw128(uint32_t off) {
    return off ^ ((off >> 3) & 0x70);
}
__device__ __forceinline__ uint32_t pkbf(float a, float b) {
    __nv_bfloat162 v;
    v.x = __float2bfloat16(a);
    v.y = __float2bfloat16(b);
    return *reinterpret_cast<uint32_t*>(&v);
}
__device__ __forceinline__ float sigf(float x) { return 1.0f / (1.0f + __expf(-x)); }

// ---------------- one-time prep: W -> fragment-ordered hi/lo ----------------
// One thread per (tile, lane). b0 = {W[n][k], W[n][k+1]}, b1 = same at k+8,
// with n = nn*8 + lane/4, k = kk*16 + (lane%4)*2.  (PTX m16n8k16 B fragment.)
__global__ void convert_Wfrag(const float* __restrict__ W) {
    int gid = blockIdx.x * blockDim.x + threadIdx.x;  // tile*32 + lane
    int lane = gid & 31;
    int tile = gid >> 5;
    int kk = tile & (NTILES_K - 1);
    int nn = tile >> 5;
    int n = nn * 8 + (lane >> 2);
    int k = kk * 16 + (lane & 3) * 2;
    const float* row = W + (size_t)n * KK + k;
    float w0 = row[0], w1 = row[1], w2 = row[8], w3 = row[9];
    float h0 = __bfloat162float(__float2bfloat16(w0));
    float h1 = __bfloat162float(__float2bfloat16(w1));
    float h2 = __bfloat162float(__float2bfloat16(w2));
    float h3 = __bfloat162float(__float2bfloat16(w3));
    uint32_t bh0 = pkbf(w0, w1), bh1 = pkbf(w2, w3);
    uint32_t bl0 = pkbf(w0 - h0, w1 - h1), bl1 = pkbf(w2 - h2, w3 - h3);
    g_WfH[gid] = (ull)bh0 | ((ull)bh1 << 32);
    g_WfL[gid] = (ull)bl0 | ((ull)bl1 << 32);
}
__global__ void init_state(const float* __restrict__ h0, const float* __restrict__ c0) {
    int b = blockIdx.x, j = threadIdx.x;
    g_h[0][b][j]    = h0[b * HH + j];
    g_c[b * HH + j] = c0[b * HH + j];
}

// ---------------- LSTM step ----------------
__global__ void __launch_bounds__(128) lstm_step(
    int t, int rd, int wr,
    const int* __restrict__ target, const float* __restrict__ emb,
    const float* __restrict__ W_ih, const float* __restrict__ W_hh,
    const float* __restrict__ b_ih, const float* __restrict__ b_hh)
{
    __shared__ float sx[4][EE];
    __shared__ float sh[4][HH];
    __shared__ float sg[4][32][4];

    int tid = threadIdx.x;
    int j0 = blockIdx.x * 32;
    int b0 = blockIdx.y * 4;

#pragma unroll
    for (int i = 0; i < 4; i++) {
        int idx = tid + i * 128;
        int bl = idx >> 7, k = idx & 127;
        int tok = target[(b0 + bl) * TT + t];
        sx[bl][k] = emb[(size_t)tok * EE + k];
    }
#pragma unroll
    for (int i = 0; i < 8; i++) {
        int idx = tid + i * 128;
        int bl = idx >> 8, j = idx & 255;
        sh[bl][j] = g_h[rd][b0 + bl][j];
    }
    __syncthreads();

    int gate = tid >> 5, jl = tid & 31;
    int row = gate * HH + j0 + jl;
    float bias = b_ih[row] + b_hh[row];
    float acc[4] = {bias, bias, bias, bias};

    const float4* wih = (const float4*)(W_ih + (size_t)row * EE);
#pragma unroll 8
    for (int kq = 0; kq < EE / 4; kq++) {
        float4 w = wih[kq];
#pragma unroll
        for (int bl = 0; bl < 4; bl++) {
            float4 x = *(const float4*)&sx[bl][kq * 4];
            acc[bl] = fmaf(w.x, x.x, acc[bl]);
            acc[bl] = fmaf(w.y, x.y, acc[bl]);
            acc[bl] = fmaf(w.z, x.z, acc[bl]);
            acc[bl] = fmaf(w.w, x.w, acc[bl]);
        }
    }
    const float4* whh = (const float4*)(W_hh + (size_t)row * HH);
#pragma unroll 8
    for (int kq = 0; kq < HH / 4; kq++) {
        float4 w = whh[kq];
#pragma unroll
        for (int bl = 0; bl < 4; bl++) {
            float4 h = *(const float4*)&sh[bl][kq * 4];
            acc[bl] = fmaf(w.x, h.x, acc[bl]);
            acc[bl] = fmaf(w.y, h.y, acc[bl]);
            acc[bl] = fmaf(w.z, h.z, acc[bl]);
            acc[bl] = fmaf(w.w, h.w, acc[bl]);
        }
    }
#pragma unroll
    for (int bl = 0; bl < 4; bl++) sg[gate][jl][bl] = acc[bl];
    __syncthreads();

    {
        int jl2 = tid >> 2, bl2 = tid & 3;
        float gi = sg[0][jl2][bl2];
        float gf = sg[1][jl2][bl2];
        float gg = sg[2][jl2][bl2];
        float go = sg[3][jl2][bl2];
        int j = j0 + jl2, b = b0 + bl2;
        float c_old = g_c[b * HH + j];
        float c_new = sigf(gf) * c_old + sigf(gi) * tanhf(gg);
        float h_new = sigf(go) * tanhf(c_new);
        g_c[b * HH + j] = c_new;
        g_h[wr][b][j]   = h_new;
        __nv_bfloat16 hi = __float2bfloat16(h_new);
        g_Ah[wr][b][j] = hi;
        g_Al[wr][b][j] = __float2bfloat16(h_new - __bfloat162float(hi));
    }
}

// ---------------- attention ----------------
__global__ void __launch_bounds__(512) attn_step(
    int cur, const float* __restrict__ enc, const int* __restrict__ lens)
{
    extern __shared__ float sm[];
    float (*se)[HH] = (float(*)[HH])sm;       // [72][256]
    float* sw   = sm + SS * HH;               // [72]
    float* part = sw + SS;                    // [2][256]
    __shared__ float shv[HH];
    __shared__ float sred;

    int b = blockIdx.x, tid = threadIdx.x;

    const float4* esrc = (const float4*)(enc + (size_t)b * SS * HH);
    float4* sdst = (float4*)se;
#pragma unroll
    for (int i = 0; i < 9; i++) sdst[tid + i * 512] = esrc[tid + i * 512];
    if (tid < HH) shv[tid] = g_h[cur][b][tid];
    __syncthreads();

    int len = lens[b];
    int w = tid >> 5, lane = tid & 31;
    for (int s = w; s < SS; s += 16) {
        float acc = 0.f;
#pragma unroll
        for (int j = lane; j < HH; j += 32) acc += shv[j] * se[s][j];
#pragma unroll
        for (int o = 16; o; o >>= 1) acc += __shfl_xor_sync(0xffffffffu, acc, o);
        if (lane == 0) sw[s] = (s < len) ? acc * 0.0625f : -1e30f;
    }
    __syncthreads();

    if (tid < 32) {
        float m = -1e30f;
        for (int s = tid; s < SS; s += 32) m = fmaxf(m, sw[s]);
#pragma unroll
        for (int o = 16; o; o >>= 1) m = fmaxf(m, __shfl_xor_sync(0xffffffffu, m, o));
        float sum = 0.f;
        for (int s = tid; s < SS; s += 32) {
            float e = __expf(sw[s] - m);
            sw[s] = e;
            sum += e;
        }
#pragma unroll
        for (int o = 16; o; o >>= 1) sum += __shfl_xor_sync(0xffffffffu, sum, o);
        if (tid == 0) sred = 1.0f / sum;
    }
    __syncthreads();

    {
        int j = tid & 255, half = tid >> 8;
        int s0 = half * 36;
        float acc = 0.f;
#pragma unroll
        for (int s = 0; s < 36; s++) acc += sw[s0 + s] * se[s0 + s][j];
        part[half * 256 + j] = acc;
    }
    __syncthreads();
    if (tid < 256) {
        float ctx = (part[tid] + part[256 + tid]) * sred;
        __nv_bfloat16 hi = __float2bfloat16(ctx);
        g_Ah[cur][b][HH + tid] = hi;
        g_Al[cur][b][HH + tid] = __float2bfloat16(ctx - __bfloat162float(hi));
    }
}

// ---------------- output projection: HMMA bf16-split GEMM ----------------
// 125 CTAs x 512 threads (16 warps). CTA tile 64M x 256N.
// Warp tile 64M x 16N (mt=4, nt=2); every B tile read ONCE per CTA as a
// single coalesced LDG.64 from fragment-ordered g_WfH/g_WfL (no smem for B).
// A (hi/lo) staged in smem via cp.async double buffer (32 KB), ldmatrix x4.
#define A_OFF_AL 8192
#define A_STAGE  16384

__global__ void __launch_bounds__(512) gemm_step(
    int t, int cur, const float* __restrict__ b_lin, float* __restrict__ out)
{
    __shared__ __align__(1024) char smc[2 * A_STAGE];   // 32 KB
    uint32_t sb = smem_u32(smc);
    int tid = threadIdx.x, wid = tid >> 5, lane = tid & 31;
    int n0g = blockIdx.x * NTILE;
    int nnBase = blockIdx.x * 32 + wid * 2;   // first n8-tile for this warp

    // ---- A chunk loader (512 threads: 1024 cp.async per chunk) ----
    auto load_chunkA = [&](int ko, int s) {
        int k0 = ko * KCH;
        uint32_t base = sb + s * A_STAGE;
        int r = tid >> 3, sg = tid & 7;          // 64 rows x 8 segs
        uint32_t o = sw128((uint32_t)(r * 128 + sg * 16));
        cp16(base + o,            &g_Ah[cur][r][k0 + sg * 8]);
        cp16(base + A_OFF_AL + o, &g_Al[cur][r][k0 + sg * 8]);
        CP_COMMIT();
    };

    float acc[4][2][4];
#pragma unroll
    for (int mt = 0; mt < 4; mt++)
#pragma unroll
        for (int nt = 0; nt < 2; nt++)
#pragma unroll
            for (int r = 0; r < 4; r++) acc[mt][nt][r] = 0.f;

    int l15 = lane & 15;
    int aKhalf = (lane >> 4) * 16;   // A ldmatrix: lanes 16-31 take k+8

    load_chunkA(0, 0);

    for (int ko = 0; ko < NCH; ko++) {
        int buf = ko & 1;

        // B fragments for this chunk: 2 nt x 4 ks, hi+lo (16 LDG.64, coalesced)
        uint2 bh[2][4], blo[2][4];
#pragma unroll
        for (int nt = 0; nt < 2; nt++) {
            size_t tbase = ((size_t)(nnBase + nt) * NTILES_K + ko * 4) * 32 + lane;
#pragma unroll
            for (int ks = 0; ks < 4; ks++) {
                bh[nt][ks]  = *(const uint2*)&g_WfH[tbase + (size_t)ks * 32];
                blo[nt][ks] = *(const uint2*)&g_WfL[tbase + (size_t)ks * 32];
            }
        }

        if (ko + 1 < NCH) {
            load_chunkA(ko + 1, buf ^ 1);
            CP_WAIT1();
        } else {
            CP_WAIT0();
        }
        __syncthreads();   // A chunk ko visible

        uint32_t base = sb + buf * A_STAGE;
#pragma unroll
        for (int ks = 0; ks < 4; ks++) {
            uint32_t ah[4][4], al[4][4];
#pragma unroll
            for (int mt = 0; mt < 4; mt++) {
                uint32_t off = sw128((uint32_t)((mt * 16 + l15) * 128 +
                                                ks * 32 + aKhalf));
                ldm_x4(base + off, ah[mt]);
                ldm_x4(base + A_OFF_AL + off, al[mt]);
            }
#pragma unroll
            for (int mt = 0; mt < 4; mt++)
#pragma unroll
                for (int nt = 0; nt < 2; nt++) {
                    mma_bf16(acc[mt][nt], ah[mt], bh[nt][ks].x,  bh[nt][ks].y);
                    mma_bf16(acc[mt][nt], ah[mt], blo[nt][ks].x, blo[nt][ks].y);
                    mma_bf16(acc[mt][nt], al[mt], bh[nt][ks].x,  bh[nt][ks].y);
                }
        }
        __syncthreads();   // done reading A buf before overwrite
    }

    // ---- epilogue: fragment regs -> gmem (float2 stores) ----
    int qr = lane >> 2, qc = lane & 3;
#pragma unroll
    for (int nt = 0; nt < 2; nt++) {
        int v = n0g + wid * 16 + nt * 8 + qc * 2;
        float2 bi = *(const float2*)&b_lin[v];
#pragma unroll
        for (int mt = 0; mt < 4; mt++) {
            int bA = mt * 16 + qr;
            int bBt = bA + 8;
            float2 lo = {acc[mt][nt][0] + bi.x, acc[mt][nt][1] + bi.y};
            float2 hi = {acc[mt][nt][2] + bi.x, acc[mt][nt][3] + bi.y};
            *(float2*)&out[((size_t)(bA * TT + t)) * VV + v]  = lo;
            *(float2*)&out[((size_t)(bBt * TT + t)) * VV + v] = hi;
        }
    }
}

// ---------------- launch ----------------
extern "C" void kernel_launch(void* const* d_in, const int* in_sizes, int n_in,
                              void* d_out, int out_size)
{
    const int*   target = (const int*)d_in[0];
    const float* enc    = (const float*)d_in[1];
    const int*   lens   = (const int*)d_in[2];
    const float* h0     = (const float*)d_in[3];
    const float* c0     = (const float*)d_in[4];
    const float* emb    = (const float*)d_in[5];
    const float* W_ih   = (const float*)d_in[6];
    const float* W_hh   = (const float*)d_in[7];
    const float* b_ih   = (const float*)d_in[8];
    const float* b_hh   = (const float*)d_in[9];
    const float* W_lin  = (const float*)d_in[10];
    const float* b_lin  = (const float*)d_in[11];
    float* out = (float*)d_out;

    const int attn_smem = (SS * HH + SS + 2 * HH) * (int)sizeof(float);
    cudaFuncSetAttribute(attn_step, cudaFuncAttributeMaxDynamicSharedMemorySize,
                         attn_smem);

    convert_Wfrag<<<NTILES_N * NTILES_K * 32 / 512, 512>>>(W_lin);
    init_state<<<BB, HH>>>(h0, c0);

    for (int t = 0; t < TT; t++) {
        int rd = t & 1, wr = rd ^ 1;
        lstm_step<<<dim3(HH / 32, BB / 4), 128>>>(t, rd, wr, target, emb,
                                                  W_ih, W_hh, b_ih, b_hh);
        attn_step<<<BB, 512, attn_smem>>>(wr, enc, lens);
        gemm_step<<<VV / NTILE, 512>>>(t, wr, b_lin, out);
    }
}